// round 12
// baseline (speedup 1.0000x reference)
#include <cuda_runtime.h>
#include <cuda_fp16.h>
#include <cstdint>

// CapsuleLayer dynamic routing, 3 rounds.
// x: [512, 1152, 8] fp32   W: [10, 1152, 8, 16] fp32   out: [10, 512, 16] fp32
//
// R11 structure (proven 97.0us) with ONE change: x repacked to fp16 with
// rq-innermost layout (caps_Xh[bg][g][b][rq] uint4 = 8 halves = full Cin
// row), making every phase-1 x warp load one full 128B line (1 wf) instead
// of a half-dense 256B span (2 wf): x wavefronts 2304 -> 576 per block.
//
// W pre-pass: caps_Wh[n][g][ip][rq][oq] uint4 (16B = 8 halves):
//   halves 0..3 = W[g*8+rq][2ip][4oq..4oq+3], 4..7 = same at i=2ip+1.
//   Phase-1 warp instr (fixed ip) reads 512B contiguous -> 4 wf/LDG.128.
// Phase 1: warp = row-octet; lane = (rq 0..7, oq 0..3); W converted once to
//   16 packed f32x2 regs, b-pair split GEMM (FMA2). Priors -> fp16 smem,
//   PSTR=16, 8B-chunk XOR swizzle: conflict-free STS.64 and LDS.64.
// Phase 2: 4 groups x 192 threads, 6 rows/thread, streamed LDS.64 rows,
//   max-free softmax (shift-invariant, |a|<~20): one fused a/e/Z/S pass per
//   round. v0 = squash(mean p). w = v0, then v0+v1 (logits additive in p).

#define NCAPS 10
#define NB    512
#define NR    1152
#define CI    8
#define CO    16
#define BT    4
#define NTHREADS 768
#define GROUPS (NB / BT)          // 128
#define TPB   192                 // threads per batch group (6 warps)
#define WPG   6
#define KPT   (NR / TPB)          // 6 rows per thread in routing
#define NWARP (NTHREADS / 32)     // 24
#define OCT   (NR / 8)            // 144 row-octets
#define JIT   (OCT / NWARP)       // 6 octets per warp
#define PSTR  16                  // halves per prior row (exact, swizzled)

// shared memory layout (bytes)
#define P_BYTES    (BT * NR * PSTR * 2)   // 147456 fp16 priors
#define SRED_OFF   P_BYTES
#define SRED_BYTES (BT * WPG * CO * 4)    // 1536
#define WRED_OFF   (SRED_OFF + SRED_BYTES)
#define WRED_BYTES (BT * WPG * 4)         // 96
#define VDOT_OFF   (WRED_OFF + WRED_BYTES)
#define VDOT_BYTES (BT * CO * 4)          // 256
#define SMEM_TOTAL (VDOT_OFF + VDOT_BYTES)

// repacked fp16 W: [NCAPS][OCT][4 ip][8 rq][4 oq] x 16B
__device__ __align__(16) uint4 caps_Wh[NCAPS * OCT * 4 * 32];
// repacked fp16 x: [GROUPS][OCT][BT][8 rq] x 16B (8 halves = Cin row)
__device__ __align__(16) uint4 caps_Xh[GROUPS * OCT * BT * 8];

struct __align__(8) H4 { __half2 a, b; };
typedef unsigned long long u64;

__device__ __forceinline__ void fma2(u64& d, u64 a, u64 b) {
    asm("fma.rn.f32x2 %0, %1, %2, %0;" : "+l"(d) : "l"(a), "l"(b));
}
__device__ __forceinline__ u64 pack2(float x) {
    u64 r; asm("mov.b64 %0, {%1, %1};" : "=l"(r) : "f"(x)); return r;
}
__device__ __forceinline__ u64 packf2(float x, float y) {
    u64 r; asm("mov.b64 %0, {%1, %2};" : "=l"(r) : "f"(x), "f"(y)); return r;
}
__device__ __forceinline__ float2 unpack2(u64 v) {
    float2 f; asm("mov.b64 {%0, %1}, %2;" : "=f"(f.x), "=f"(f.y) : "l"(v));
    return f;
}
__device__ __forceinline__ u64 h2pk(uint32_t h) {    // half2 -> packed f32x2
    const float2 f = __half22float2(*(const __half2*)&h);
    return packf2(f.x, f.y);
}
__device__ __forceinline__ void bar_group(int id) {
    asm volatile("bar.sync %0, %1;" :: "r"(id), "r"(TPB) : "memory");
}

// Load logical row r (8B-chunk swizzled) into f[16].
__device__ __forceinline__ void load_row_sw(const __half* pb, int r,
                                            float f[CO]) {
    const uint2* base = (const uint2*)(pb + (size_t)r * PSTR);
    const int d = (r >> 2) & 3;
    #pragma unroll
    for (int q = 0; q < 4; ++q) {
        const uint2 u = base[q ^ d];
        const float2 f0 = __half22float2(*(const __half2*)&u.x);
        const float2 f1 = __half22float2(*(const __half2*)&u.y);
        f[q*4+0] = f0.x; f[q*4+1] = f0.y; f[q*4+2] = f1.x; f[q*4+3] = f1.y;
    }
}

// Split-exchange reduce of S[16] over 32 lanes: 16 shfl total.
__device__ __forceinline__ void reduce_s16(float S[CO], int lane,
                                           float* sred_warp) {
    const bool h16 = lane & 16;
    #pragma unroll
    for (int j = 0; j < 8; ++j) {
        const float snd = h16 ? S[j] : S[j + 8];
        const float kp  = h16 ? S[j + 8] : S[j];
        S[j] = kp + __shfl_xor_sync(0xffffffffu, snd, 16);
    }
    const bool h8 = lane & 8;
    #pragma unroll
    for (int j = 0; j < 4; ++j) {
        const float snd = h8 ? S[j] : S[j + 4];
        const float kp  = h8 ? S[j + 4] : S[j];
        S[j] = kp + __shfl_xor_sync(0xffffffffu, snd, 8);
    }
    const bool h4 = lane & 4;
    #pragma unroll
    for (int j = 0; j < 2; ++j) {
        const float snd = h4 ? S[j] : S[j + 2];
        const float kp  = h4 ? S[j + 2] : S[j];
        S[j] = kp + __shfl_xor_sync(0xffffffffu, snd, 4);
    }
    const bool h2 = lane & 2;
    {
        const float snd = h2 ? S[0] : S[1];
        const float kp  = h2 ? S[1] : S[0];
        S[0] = kp + __shfl_xor_sync(0xffffffffu, snd, 2);
    }
    S[0] += __shfl_xor_sync(0xffffffffu, S[0], 1);
    const int comp = ((lane >> 4) & 1) * 8 + ((lane >> 3) & 1) * 4 +
                     ((lane >> 2) & 1) * 2 + ((lane >> 1) & 1);
    if (!(lane & 1)) sred_warp[comp] = S[0];
}

// ---------- W repack (fp32 -> fp16): one thread per 16B output ----------
__global__ void __launch_bounds__(256)
repack_w_kernel(const float* __restrict__ W) {
    const int idx = blockIdx.x * blockDim.x + threadIdx.x;
    if (idx >= NCAPS * OCT * 4 * 32) return;
    const int oq = idx & 3;
    const int rq = (idx >> 2) & 7;
    const int ip = (idx >> 5) & 3;
    const int rb = idx >> 7;               // n*OCT + g
    const float* row = W + (size_t)(rb * 8 + rq) * 128;
    const float4 fe = *(const float4*)(row + (2*ip)     * 16 + 4*oq);
    const float4 fo = *(const float4*)(row + (2*ip + 1) * 16 + 4*oq);
    __half2 h0 = __floats2half2_rn(fe.x, fe.y);
    __half2 h1 = __floats2half2_rn(fe.z, fe.w);
    __half2 h2 = __floats2half2_rn(fo.x, fo.y);
    __half2 h3 = __floats2half2_rn(fo.z, fo.w);
    uint4 o;
    o.x = *(uint32_t*)&h0; o.y = *(uint32_t*)&h1;
    o.z = *(uint32_t*)&h2; o.w = *(uint32_t*)&h3;
    caps_Wh[idx] = o;
}

// ---------- x repack (fp32 -> fp16, rq innermost): thread per 16B ----------
__global__ void __launch_bounds__(256)
repack_x_kernel(const float* __restrict__ x) {
    const int idx = blockIdx.x * blockDim.x + threadIdx.x;
    if (idx >= GROUPS * OCT * BT * 8) return;
    const int rq = idx & 7;
    const int b4 = (idx >> 3) & 3;
    const int tt = idx >> 5;               // bg*OCT + g
    const int g  = tt % OCT;
    const int bg = tt / OCT;
    const int batch = bg * BT + b4;
    const int r = g * 8 + rq;
    const float4* src = (const float4*)(x + ((size_t)batch * NR + r) * CI);
    const float4 x0 = src[0], x1 = src[1];
    __half2 h0 = __floats2half2_rn(x0.x, x0.y);
    __half2 h1 = __floats2half2_rn(x0.z, x0.w);
    __half2 h2 = __floats2half2_rn(x1.x, x1.y);
    __half2 h3 = __floats2half2_rn(x1.z, x1.w);
    uint4 o;
    o.x = *(uint32_t*)&h0; o.y = *(uint32_t*)&h1;
    o.z = *(uint32_t*)&h2; o.w = *(uint32_t*)&h3;
    caps_Xh[idx] = o;
}

__global__ void __launch_bounds__(NTHREADS, 1)
caps_kernel(float* __restrict__ out) {
    extern __shared__ char smem[];
    __half* p   = (__half*)smem;
    float* sred = (float*)(smem + SRED_OFF);
    float* wred = (float*)(smem + WRED_OFF);
    float* vdot = (float*)(smem + VDOT_OFF);

    const int n  = blockIdx.y;
    const int bg = blockIdx.x;
    const int b0 = bg * BT;
    const int t  = threadIdx.x;
    const int wid  = t >> 5;
    const int lane = t & 31;

    // ======== Phase 1: priors GEMM (octet mapping, fp16 W + fp16 x) ========
    // lane = (rq 0..7, oq 0..3)
    {
        const int rq = lane >> 2;
        const int oq = lane & 3;
        #pragma unroll 1
        for (int j = 0; j < JIT; ++j) {
            const int g = wid + j * NWARP;
            const int r = g * 8 + rq;
            const int d = (r >> 2) & 3;
            const int choff = (oq ^ d) << 2;          // halves within row
            // W: 4 LDG.128, each warp-instr covers 512B contiguous
            const uint4* wh =
                caps_Wh + ((size_t)(n * OCT + g) * 4) * 32 + rq * 4 + oq;
            uint4 wc4[4];
            #pragma unroll
            for (int ip = 0; ip < 4; ++ip) wc4[ip] = wh[ip * 32];
            // convert once: 16 packed f32x2 (i ascending)
            u64 wpk[16];
            #pragma unroll
            for (int ip = 0; ip < 4; ++ip) {
                wpk[4*ip + 0] = h2pk(wc4[ip].x);   // i=2ip,   o0 o1
                wpk[4*ip + 1] = h2pk(wc4[ip].y);   // i=2ip,   o2 o3
                wpk[4*ip + 2] = h2pk(wc4[ip].z);   // i=2ip+1, o0 o1
                wpk[4*ip + 3] = h2pk(wc4[ip].w);   // i=2ip+1, o2 o3
            }
            // x: one uint4 per batch; warp-instr = 8 consecutive uint4 = 1 wf
            const uint4* xh =
                caps_Xh + (((size_t)bg * OCT + g) * BT) * 8 + rq;

            // b-pair split keeps live registers bounded
            #pragma unroll
            for (int bp = 0; bp < 2; ++bp) {
                float xf[2][CI];
                #pragma unroll
                for (int bb = 0; bb < 2; ++bb) {
                    const uint4 xq = xh[(bp * 2 + bb) * 8];
                    const float2 e0 = __half22float2(*(const __half2*)&xq.x);
                    const float2 e1 = __half22float2(*(const __half2*)&xq.y);
                    const float2 e2 = __half22float2(*(const __half2*)&xq.z);
                    const float2 e3 = __half22float2(*(const __half2*)&xq.w);
                    xf[bb][0]=e0.x; xf[bb][1]=e0.y; xf[bb][2]=e1.x; xf[bb][3]=e1.y;
                    xf[bb][4]=e2.x; xf[bb][5]=e2.y; xf[bb][6]=e3.x; xf[bb][7]=e3.y;
                }
                u64 acc[2][2];
                acc[0][0]=0ull; acc[0][1]=0ull; acc[1][0]=0ull; acc[1][1]=0ull;
                #pragma unroll
                for (int i = 0; i < CI; ++i) {
                    const u64 wlo = wpk[(i >> 1) * 4 + (i & 1) * 2 + 0];
                    const u64 whi = wpk[(i >> 1) * 4 + (i & 1) * 2 + 1];
                    #pragma unroll
                    for (int bb = 0; bb < 2; ++bb) {
                        const u64 xx = pack2(xf[bb][i]);
                        fma2(acc[bb][0], xx, wlo);
                        fma2(acc[bb][1], xx, whi);
                    }
                }
                #pragma unroll
                for (int bb = 0; bb < 2; ++bb) {
                    const int b = bp * 2 + bb;
                    const float2 f0 = unpack2(acc[bb][0]);
                    const float2 f1 = unpack2(acc[bb][1]);
                    H4 h;
                    h.a = __floats2half2_rn(f0.x, f0.y);
                    h.b = __floats2half2_rn(f1.x, f1.y);
                    *(H4*)(p + (size_t)(b * NR + r) * PSTR + choff) = h;
                }
            }
        }
    }
    __syncthreads();

    // ======== Phase 2: routing, streamed rows, max-free softmax ========
    const int b    = t / TPB;      // 0..3
    const int tb   = t % TPB;      // 0..191
    const int wl   = tb >> 5;      // warp in group 0..5
    const int bid  = b + 1;
    const __half* pb = p + (size_t)b * NR * PSTR;
    float* sredb = sred + b * WPG * CO;
    float* wredb = wred + b * WPG;
    float* vdotb = vdot + b * CO;

    // ---- v0 = squash(mean_r p_r): one streamed pass ----
    {
        float S[CO];
        #pragma unroll
        for (int o = 0; o < CO; ++o) S[o] = 0.f;
        #pragma unroll
        for (int k = 0; k < KPT; ++k) {
            float f[CO];
            load_row_sw(pb, tb + k * TPB, f);
            #pragma unroll
            for (int o = 0; o < CO; ++o) S[o] += f[o];
        }
        reduce_s16(S, lane, sredb + wl * CO);
        bar_group(bid);
        if (tb < CO) {
            float s = 0.f;
            #pragma unroll
            for (int w = 0; w < WPG; ++w) s += sredb[w * CO + tb];
            const float v = s * (1.0f / NR);
            float sq = v * v;
            #pragma unroll
            for (int off = 8; off; off >>= 1)
                sq += __shfl_xor_sync(0xffffu, sq, off);
            const float coef = sq / ((1.f + sq) * sqrtf(sq));
            vdotb[tb] = v * coef;
        }
        bar_group(bid);
    }

    // ---- rounds 1 and 2: single fused streamed pass per round ----
    #pragma unroll
    for (int round = 0; round < 2; ++round) {
        float vd[CO];
        #pragma unroll
        for (int o = 0; o < CO; ++o) vd[o] = vdotb[o];

        float S[CO];
        #pragma unroll
        for (int o = 0; o < CO; ++o) S[o] = 0.f;
        float zloc = 0.f;

        #pragma unroll
        for (int k = 0; k < KPT; ++k) {
            float f[CO];
            load_row_sw(pb, tb + k * TPB, f);
            float a = 0.f;
            #pragma unroll
            for (int o = 0; o < CO; ++o) a += f[o] * vd[o];
            const float e = __expf(a);      // max-free: |a| <~ 20, safe
            zloc += e;
            #pragma unroll
            for (int o = 0; o < CO; ++o) S[o] += e * f[o];
        }
        #pragma unroll
        for (int off = 16; off; off >>= 1)
            zloc += __shfl_xor_sync(0xffffffffu, zloc, off);
        if (lane == 0) wredb[wl] = zloc;
        reduce_s16(S, lane, sredb + wl * CO);
        bar_group(bid);

        if (tb < CO) {
            float s = 0.f;
            #pragma unroll
            for (int w = 0; w < WPG; ++w) s += sredb[w * CO + tb];
            float Z = wredb[0];
            #pragma unroll
            for (int w = 1; w < WPG; ++w) Z += wredb[w];
            const float v = s / Z;
            float sq = v * v;
            #pragma unroll
            for (int off = 8; off; off >>= 1)
                sq += __shfl_xor_sync(0xffffu, sq, off);
            const float coef = sq / ((1.f + sq) * sqrtf(sq));
            const float res = v * coef;
            if (round == 0)
                vdotb[tb] += res;                       // w = v0 + v1
            else
                out[((size_t)n * NB + (b0 + b)) * CO + tb] = res;
        }
        bar_group(bid);
    }
}

extern "C" void kernel_launch(void* const* d_in, const int* in_sizes, int n_in,
                              void* d_out, int out_size) {
    (void)in_sizes; (void)n_in; (void)out_size;
    const float* x = (const float*)d_in[0];
    const float* W = (const float*)d_in[1];
    float* out = (float*)d_out;

    const int totalW = NCAPS * OCT * 4 * 32;
    repack_w_kernel<<<(totalW + 255) / 256, 256>>>(W);
    const int totalX = GROUPS * OCT * BT * 8;
    repack_x_kernel<<<(totalX + 255) / 256, 256>>>(x);

    cudaFuncSetAttribute(caps_kernel,
                         cudaFuncAttributeMaxDynamicSharedMemorySize, SMEM_TOTAL);
    dim3 grid(GROUPS, NCAPS);
    caps_kernel<<<grid, NTHREADS, SMEM_TOTAL>>>(out);
}

// round 13
// speedup vs baseline: 1.0403x; 1.0403x over previous
#include <cuda_runtime.h>
#include <cuda_fp16.h>
#include <cstdint>

// CapsuleLayer dynamic routing, 3 rounds.
// x: [512, 1152, 8] fp32   W: [10, 1152, 8, 16] fp32   out: [10, 512, 16] fp32
//
// R11 structure (proven 97.0us) + fused S0:
// W pre-pass (fp16): caps_Wh[n][g][ip][rq][oq] uint4 (16B = 8 halves):
//   halves 0..3 = W[g*8+rq][2ip][4oq..4oq+3], 4..7 = same at i=2ip+1.
//   Phase-1 warp instr (fixed ip) reads 512B contiguous -> 4 wf/LDG.128.
// Phase 1: warp = row-octet; lane = (rq 0..7, oq 0..3); W converted
//   JUST-IN-TIME per i (frees 32 regs vs held wpk[16], making room for the
//   fused S0 accumulators); b-pair split GEMM (FMA2). S0 = sum_r p_r
//   accumulated in fp32 from acc (16 regs), reduced over rq by 48 shfl +
//   one STS.128 per (warp,b) at phase end. Priors -> fp16 smem, PSTR=16,
//   8B-chunk XOR swizzle: conflict-free STS.64 and LDS.64.
// Phase 2: v0 = squash(S0/NR) directly from s0red (NO streamed v0 pass --
//   one of three routing passes eliminated, and v0 now comes from fp32
//   pre-rounding priors, closer to reference). Rounds 1-2: streamed LDS.64
//   rows, max-free softmax (shift-invariant, |a|<~20): one fused a/e/Z/S
//   pass per round. w = v0, then v0+v1 (logits additive in p).

#define NCAPS 10
#define NB    512
#define NR    1152
#define CI    8
#define CO    16
#define BT    4
#define NTHREADS 768
#define GROUPS (NB / BT)          // 128
#define TPB   192                 // threads per batch group (6 warps)
#define WPG   6
#define KPT   (NR / TPB)          // 6 rows per thread in routing
#define NWARP (NTHREADS / 32)     // 24
#define OCT   (NR / 8)            // 144 row-octets
#define JIT   (OCT / NWARP)       // 6 octets per warp
#define PSTR  16                  // halves per prior row (exact, swizzled)

// shared memory layout (bytes)
#define P_BYTES    (BT * NR * PSTR * 2)   // 147456 fp16 priors
#define SRED_OFF   P_BYTES
#define SRED_BYTES (BT * WPG * CO * 4)    // 1536
#define WRED_OFF   (SRED_OFF + SRED_BYTES)
#define WRED_BYTES (BT * WPG * 4)         // 96
#define VDOT_OFF   (WRED_OFF + WRED_BYTES)
#define VDOT_BYTES (BT * CO * 4)          // 256
#define S0_OFF     (VDOT_OFF + VDOT_BYTES)
#define S0_BYTES   (NWARP * BT * CO * 4)  // 6144 per-warp fp32 S0 partials
#define SMEM_TOTAL (S0_OFF + S0_BYTES)

// repacked fp16 W: [NCAPS][OCT][4 ip][8 rq][4 oq] x 16B
__device__ __align__(16) uint4 caps_Wh[NCAPS * OCT * 4 * 32];

struct __align__(8) H4 { __half2 a, b; };
typedef unsigned long long u64;

__device__ __forceinline__ void fma2(u64& d, u64 a, u64 b) {
    asm("fma.rn.f32x2 %0, %1, %2, %0;" : "+l"(d) : "l"(a), "l"(b));
}
__device__ __forceinline__ void add2(u64& d, u64 a) {
    asm("add.rn.f32x2 %0, %0, %1;" : "+l"(d) : "l"(a));
}
__device__ __forceinline__ u64 pack2(float x) {
    u64 r; asm("mov.b64 %0, {%1, %1};" : "=l"(r) : "f"(x)); return r;
}
__device__ __forceinline__ u64 packf2(float x, float y) {
    u64 r; asm("mov.b64 %0, {%1, %2};" : "=l"(r) : "f"(x), "f"(y)); return r;
}
__device__ __forceinline__ float2 unpack2(u64 v) {
    float2 f; asm("mov.b64 {%0, %1}, %2;" : "=f"(f.x), "=f"(f.y) : "l"(v));
    return f;
}
__device__ __forceinline__ u64 h2pk(uint32_t h) {    // half2 -> packed f32x2
    const float2 f = __half22float2(*(const __half2*)&h);
    return packf2(f.x, f.y);
}
__device__ __forceinline__ void bar_group(int id) {
    asm volatile("bar.sync %0, %1;" :: "r"(id), "r"(TPB) : "memory");
}

// Load logical row r (8B-chunk swizzled) into f[16].
__device__ __forceinline__ void load_row_sw(const __half* pb, int r,
                                            float f[CO]) {
    const uint2* base = (const uint2*)(pb + (size_t)r * PSTR);
    const int d = (r >> 2) & 3;
    #pragma unroll
    for (int q = 0; q < 4; ++q) {
        const uint2 u = base[q ^ d];
        const float2 f0 = __half22float2(*(const __half2*)&u.x);
        const float2 f1 = __half22float2(*(const __half2*)&u.y);
        f[q*4+0] = f0.x; f[q*4+1] = f0.y; f[q*4+2] = f1.x; f[q*4+3] = f1.y;
    }
}

// Split-exchange reduce of S[16] over 32 lanes: 16 shfl total.
__device__ __forceinline__ void reduce_s16(float S[CO], int lane,
                                           float* sred_warp) {
    const bool h16 = lane & 16;
    #pragma unroll
    for (int j = 0; j < 8; ++j) {
        const float snd = h16 ? S[j] : S[j + 8];
        const float kp  = h16 ? S[j + 8] : S[j];
        S[j] = kp + __shfl_xor_sync(0xffffffffu, snd, 16);
    }
    const bool h8 = lane & 8;
    #pragma unroll
    for (int j = 0; j < 4; ++j) {
        const float snd = h8 ? S[j] : S[j + 4];
        const float kp  = h8 ? S[j + 4] : S[j];
        S[j] = kp + __shfl_xor_sync(0xffffffffu, snd, 8);
    }
    const bool h4 = lane & 4;
    #pragma unroll
    for (int j = 0; j < 2; ++j) {
        const float snd = h4 ? S[j] : S[j + 2];
        const float kp  = h4 ? S[j + 2] : S[j];
        S[j] = kp + __shfl_xor_sync(0xffffffffu, snd, 4);
    }
    const bool h2 = lane & 2;
    {
        const float snd = h2 ? S[0] : S[1];
        const float kp  = h2 ? S[1] : S[0];
        S[0] = kp + __shfl_xor_sync(0xffffffffu, snd, 2);
    }
    S[0] += __shfl_xor_sync(0xffffffffu, S[0], 1);
    const int comp = ((lane >> 4) & 1) * 8 + ((lane >> 3) & 1) * 4 +
                     ((lane >> 2) & 1) * 2 + ((lane >> 1) & 1);
    if (!(lane & 1)) sred_warp[comp] = S[0];
}

// ---------- W repack (fp32 -> fp16): 2 outputs per thread, MLP 4 ----------
#define WTOTAL (NCAPS * OCT * 4 * 32)
__global__ void __launch_bounds__(256)
repack_w_kernel(const float* __restrict__ W) {
    const int tid = blockIdx.x * blockDim.x + threadIdx.x;
    #pragma unroll
    for (int h = 0; h < 2; ++h) {
        const int idx = tid + h * (WTOTAL / 2);
        const int oq = idx & 3;
        const int rq = (idx >> 2) & 7;
        const int ip = (idx >> 5) & 3;
        const int rb = idx >> 7;               // n*OCT + g
        const float* row = W + (size_t)(rb * 8 + rq) * 128;
        const float4 fe = *(const float4*)(row + (2*ip)     * 16 + 4*oq);
        const float4 fo = *(const float4*)(row + (2*ip + 1) * 16 + 4*oq);
        __half2 h0 = __floats2half2_rn(fe.x, fe.y);
        __half2 h1 = __floats2half2_rn(fe.z, fe.w);
        __half2 h2 = __floats2half2_rn(fo.x, fo.y);
        __half2 h3 = __floats2half2_rn(fo.z, fo.w);
        uint4 o;
        o.x = *(uint32_t*)&h0; o.y = *(uint32_t*)&h1;
        o.z = *(uint32_t*)&h2; o.w = *(uint32_t*)&h3;
        caps_Wh[idx] = o;
    }
}

__global__ void __launch_bounds__(NTHREADS, 1)
caps_kernel(const float* __restrict__ x,
            float* __restrict__ out) {
    extern __shared__ char smem[];
    __half* p    = (__half*)smem;
    float* sred  = (float*)(smem + SRED_OFF);
    float* wred  = (float*)(smem + WRED_OFF);
    float* vdot  = (float*)(smem + VDOT_OFF);
    float* s0red = (float*)(smem + S0_OFF);   // [warp][b][16 o] fp32

    const int n  = blockIdx.y;
    const int b0 = blockIdx.x * BT;
    const int t  = threadIdx.x;
    const int wid  = t >> 5;
    const int lane = t & 31;

    // ======== Phase 1: priors GEMM + fused fp32 S0 (octet mapping) ========
    // lane = (rq 0..7, oq 0..3)
    {
        const int rq = lane >> 2;
        const int oq = lane & 3;
        u64 s0[BT][2];                         // fused S0, o-quad per b
        #pragma unroll
        for (int b = 0; b < BT; ++b) { s0[b][0] = 0ull; s0[b][1] = 0ull; }

        #pragma unroll 1
        for (int j = 0; j < JIT; ++j) {
            const int g = wid + j * NWARP;
            const int r = g * 8 + rq;
            const int d = (r >> 2) & 3;
            const int choff = (oq ^ d) << 2;          // halves within row
            // W: 4 LDG.128, each warp-instr covers 512B contiguous
            const uint4* wh =
                caps_Wh + ((size_t)(n * OCT + g) * 4) * 32 + rq * 4 + oq;
            uint4 wc4[4];
            #pragma unroll
            for (int ip = 0; ip < 4; ++ip) wc4[ip] = wh[ip * 32];

            // b-pair split; W converted JIT per i (frees regs for s0)
            #pragma unroll
            for (int bp = 0; bp < 2; ++bp) {
                float xv[2][CI];
                #pragma unroll
                for (int bb = 0; bb < 2; ++bb) {
                    const int b = bp * 2 + bb;
                    const float4* xp =
                        (const float4*)(x + ((size_t)(b0 + b) * NR + r) * CI);
                    const float4 x0 = xp[0], x1 = xp[1];
                    xv[bb][0]=x0.x; xv[bb][1]=x0.y; xv[bb][2]=x0.z; xv[bb][3]=x0.w;
                    xv[bb][4]=x1.x; xv[bb][5]=x1.y; xv[bb][6]=x1.z; xv[bb][7]=x1.w;
                }
                u64 acc[2][2];
                acc[0][0]=0ull; acc[0][1]=0ull; acc[1][0]=0ull; acc[1][1]=0ull;
                #pragma unroll
                for (int i = 0; i < CI; ++i) {
                    const int ip = i >> 1;
                    const u64 wlo = h2pk((i & 1) ? wc4[ip].z : wc4[ip].x);
                    const u64 whi = h2pk((i & 1) ? wc4[ip].w : wc4[ip].y);
                    #pragma unroll
                    for (int bb = 0; bb < 2; ++bb) {
                        const u64 xx = pack2(xv[bb][i]);
                        fma2(acc[bb][0], xx, wlo);
                        fma2(acc[bb][1], xx, whi);
                    }
                }
                #pragma unroll
                for (int bb = 0; bb < 2; ++bb) {
                    const int b = bp * 2 + bb;
                    add2(s0[b][0], acc[bb][0]);        // fused S0 (fp32)
                    add2(s0[b][1], acc[bb][1]);
                    const float2 f0 = unpack2(acc[bb][0]);
                    const float2 f1 = unpack2(acc[bb][1]);
                    H4 h;
                    h.a = __floats2half2_rn(f0.x, f0.y);
                    h.b = __floats2half2_rn(f1.x, f1.y);
                    *(H4*)(p + (size_t)(b * NR + r) * PSTR + choff) = h;
                }
            }
        }
        // reduce s0 over rq (lane bits 2..4); rq==0 lanes store o-quad
        #pragma unroll
        for (int b = 0; b < BT; ++b) {
            float2 f0 = unpack2(s0[b][0]);
            float2 f1 = unpack2(s0[b][1]);
            #pragma unroll
            for (int m = 4; m <= 16; m <<= 1) {
                f0.x += __shfl_xor_sync(0xffffffffu, f0.x, m);
                f0.y += __shfl_xor_sync(0xffffffffu, f0.y, m);
                f1.x += __shfl_xor_sync(0xffffffffu, f1.x, m);
                f1.y += __shfl_xor_sync(0xffffffffu, f1.y, m);
            }
            if (rq == 0) {
                float4 o; o.x = f0.x; o.y = f0.y; o.z = f1.x; o.w = f1.y;
                *(float4*)(s0red + (wid * BT + b) * CO + oq * 4) = o;
            }
        }
    }
    __syncthreads();

    // ======== Phase 2: routing, streamed rows, max-free softmax ========
    const int b    = t / TPB;      // 0..3
    const int tb   = t % TPB;      // 0..191
    const int wl   = tb >> 5;      // warp in group 0..5
    const int bid  = b + 1;
    const __half* pb = p + (size_t)b * NR * PSTR;
    float* sredb = sred + b * WPG * CO;
    float* wredb = wred + b * WPG;
    float* vdotb = vdot + b * CO;

    // ---- v0 = squash(mean_r p_r) directly from fused S0 partials ----
    if (tb < CO) {
        float s = 0.f;
        #pragma unroll
        for (int w = 0; w < NWARP; ++w)
            s += s0red[(w * BT + b) * CO + tb];
        const float v = s * (1.0f / NR);
        float sq = v * v;
        #pragma unroll
        for (int off = 8; off; off >>= 1)
            sq += __shfl_xor_sync(0xffffu, sq, off);
        const float coef = sq / ((1.f + sq) * sqrtf(sq));
        vdotb[tb] = v * coef;
    }
    bar_group(bid);

    // ---- rounds 1 and 2: single fused streamed pass per round ----
    #pragma unroll
    for (int round = 0; round < 2; ++round) {
        float vd[CO];
        #pragma unroll
        for (int o = 0; o < CO; ++o) vd[o] = vdotb[o];

        float S[CO];
        #pragma unroll
        for (int o = 0; o < CO; ++o) S[o] = 0.f;
        float zloc = 0.f;

        #pragma unroll
        for (int k = 0; k < KPT; ++k) {
            float f[CO];
            load_row_sw(pb, tb + k * TPB, f);
            float a = 0.f;
            #pragma unroll
            for (int o = 0; o < CO; ++o) a += f[o] * vd[o];
            const float e = __expf(a);      // max-free: |a| <~ 20, safe
            zloc += e;
            #pragma unroll
            for (int o = 0; o < CO; ++o) S[o] += e * f[o];
        }
        #pragma unroll
        for (int off = 16; off; off >>= 1)
            zloc += __shfl_xor_sync(0xffffffffu, zloc, off);
        if (lane == 0) wredb[wl] = zloc;
        reduce_s16(S, lane, sredb + wl * CO);
        bar_group(bid);

        if (tb < CO) {
            float s = 0.f;
            #pragma unroll
            for (int w = 0; w < WPG; ++w) s += sredb[w * CO + tb];
            float Z = wredb[0];
            #pragma unroll
            for (int w = 1; w < WPG; ++w) Z += wredb[w];
            const float v = s / Z;
            float sq = v * v;
            #pragma unroll
            for (int off = 8; off; off >>= 1)
                sq += __shfl_xor_sync(0xffffu, sq, off);
            const float coef = sq / ((1.f + sq) * sqrtf(sq));
            const float res = v * coef;
            if (round == 0)
                vdotb[tb] += res;                       // w = v0 + v1
            else
                out[((size_t)n * NB + (b0 + b)) * CO + tb] = res;
        }
        bar_group(bid);
    }
}

extern "C" void kernel_launch(void* const* d_in, const int* in_sizes, int n_in,
                              void* d_out, int out_size) {
    (void)in_sizes; (void)n_in; (void)out_size;
    const float* x = (const float*)d_in[0];
    const float* W = (const float*)d_in[1];
    float* out = (float*)d_out;

    repack_w_kernel<<<WTOTAL / 2 / 256, 256>>>(W);

    cudaFuncSetAttribute(caps_kernel,
                         cudaFuncAttributeMaxDynamicSharedMemorySize, SMEM_TOTAL);
    dim3 grid(GROUPS, NCAPS);
    caps_kernel<<<grid, NTHREADS, SMEM_TOTAL>>>(x, out);
}

// round 14
// speedup vs baseline: 1.0989x; 1.0563x over previous
#include <cuda_runtime.h>
#include <cuda_fp16.h>
#include <cstdint>

// CapsuleLayer dynamic routing, 3 rounds.
// x: [512, 1152, 8] fp32   W: [10, 1152, 8, 16] fp32   out: [10, 512, 16] fp32
//
// R11 macro-structure (proven 97.0us) + issue-slot micro-cuts:
//   - routing rows loaded via 2x LDS.128 (16B-chunk XOR swizzle, R9-verified
//     conflict-free), scalar f32 math kept (no packed-mov churn),
//   - vd fetched as 4x LDS.128 per round,
//   - repack_w at 2 outputs/thread.
// W pre-pass (fp16): caps_Wh[n][g][ip][rq][oq] uint4 (16B = 8 halves):
//   halves 0..3 = W[g*8+rq][2ip][4oq..4oq+3], 4..7 = same at i=2ip+1.
//   Phase-1 warp instr (fixed ip) reads 512B contiguous -> 4 wf/LDG.128.
// Phase 1: warp = row-octet; lane = (rq 0..7, oq 0..3); W converted once to
//   16 packed f32x2 regs, b-pair split GEMM (FMA2). Priors -> fp16 smem,
//   PSTR=16, 16B-chunk XOR swizzle (chunk q of row r at q ^ ((r>>2)&1)):
//   conflict-free STS.64 and LDS.128.
// Phase 2: 4 groups x 192 threads, 6 rows/thread, three streamed passes
//   (v0, round1, round2), max-free softmax (shift-invariant, |a|<~20):
//   one fused a/e/Z/S pass per round. w = v0, then v0+v1.

#define NCAPS 10
#define NB    512
#define NR    1152
#define CI    8
#define CO    16
#define BT    4
#define NTHREADS 768
#define GROUPS (NB / BT)          // 128
#define TPB   192                 // threads per batch group (6 warps)
#define WPG   6
#define KPT   (NR / TPB)          // 6 rows per thread in routing
#define NWARP (NTHREADS / 32)     // 24
#define OCT   (NR / 8)            // 144 row-octets
#define JIT   (OCT / NWARP)       // 6 octets per warp
#define PSTR  16                  // halves per prior row (exact, swizzled)

// shared memory layout (bytes)
#define P_BYTES    (BT * NR * PSTR * 2)   // 147456 fp16 priors
#define SRED_OFF   P_BYTES
#define SRED_BYTES (BT * WPG * CO * 4)    // 1536
#define WRED_OFF   (SRED_OFF + SRED_BYTES)
#define WRED_BYTES (BT * WPG * 4)         // 96
#define VDOT_OFF   (WRED_OFF + WRED_BYTES)
#define VDOT_BYTES (BT * CO * 4)          // 256 (16B-aligned per group)
#define SMEM_TOTAL (VDOT_OFF + VDOT_BYTES)

// repacked fp16 W: [NCAPS][OCT][4 ip][8 rq][4 oq] x 16B
__device__ __align__(16) uint4 caps_Wh[NCAPS * OCT * 4 * 32];

struct __align__(8) H4 { __half2 a, b; };
typedef unsigned long long u64;

__device__ __forceinline__ void fma2(u64& d, u64 a, u64 b) {
    asm("fma.rn.f32x2 %0, %1, %2, %0;" : "+l"(d) : "l"(a), "l"(b));
}
__device__ __forceinline__ u64 pack2(float x) {
    u64 r; asm("mov.b64 %0, {%1, %1};" : "=l"(r) : "f"(x)); return r;
}
__device__ __forceinline__ u64 packf2(float x, float y) {
    u64 r; asm("mov.b64 %0, {%1, %2};" : "=l"(r) : "f"(x), "f"(y)); return r;
}
__device__ __forceinline__ float2 unpack2(u64 v) {
    float2 f; asm("mov.b64 {%0, %1}, %2;" : "=f"(f.x), "=f"(f.y) : "l"(v));
    return f;
}
__device__ __forceinline__ u64 h2pk(uint32_t h) {    // half2 -> packed f32x2
    const float2 f = __half22float2(*(const __half2*)&h);
    return packf2(f.x, f.y);
}
__device__ __forceinline__ void bar_group(int id) {
    asm volatile("bar.sync %0, %1;" :: "r"(id), "r"(TPB) : "memory");
}

// Load logical row r (16B-chunk swizzled) into f[16] via 2x LDS.128.
__device__ __forceinline__ void load_row_sw(const __half* pb, int r,
                                            float f[CO]) {
    const uint4* base = (const uint4*)(pb + (size_t)r * PSTR);
    const int s = (r >> 2) & 1;
    const uint4 u0 = base[s];        // logical chunk 0
    const uint4 u1 = base[s ^ 1];    // logical chunk 1
    const uint32_t hs[8] = {u0.x, u0.y, u0.z, u0.w, u1.x, u1.y, u1.z, u1.w};
    #pragma unroll
    for (int j = 0; j < 8; ++j) {
        const float2 ff = __half22float2(*(const __half2*)&hs[j]);
        f[2*j]   = ff.x;
        f[2*j+1] = ff.y;
    }
}

// Split-exchange reduce of S[16] over 32 lanes: 16 shfl total.
__device__ __forceinline__ void reduce_s16(float S[CO], int lane,
                                           float* sred_warp) {
    const bool h16 = lane & 16;
    #pragma unroll
    for (int j = 0; j < 8; ++j) {
        const float snd = h16 ? S[j] : S[j + 8];
        const float kp  = h16 ? S[j + 8] : S[j];
        S[j] = kp + __shfl_xor_sync(0xffffffffu, snd, 16);
    }
    const bool h8 = lane & 8;
    #pragma unroll
    for (int j = 0; j < 4; ++j) {
        const float snd = h8 ? S[j] : S[j + 4];
        const float kp  = h8 ? S[j + 4] : S[j];
        S[j] = kp + __shfl_xor_sync(0xffffffffu, snd, 8);
    }
    const bool h4 = lane & 4;
    #pragma unroll
    for (int j = 0; j < 2; ++j) {
        const float snd = h4 ? S[j] : S[j + 2];
        const float kp  = h4 ? S[j + 2] : S[j];
        S[j] = kp + __shfl_xor_sync(0xffffffffu, snd, 4);
    }
    const bool h2 = lane & 2;
    {
        const float snd = h2 ? S[0] : S[1];
        const float kp  = h2 ? S[1] : S[0];
        S[0] = kp + __shfl_xor_sync(0xffffffffu, snd, 2);
    }
    S[0] += __shfl_xor_sync(0xffffffffu, S[0], 1);
    const int comp = ((lane >> 4) & 1) * 8 + ((lane >> 3) & 1) * 4 +
                     ((lane >> 2) & 1) * 2 + ((lane >> 1) & 1);
    if (!(lane & 1)) sred_warp[comp] = S[0];
}

// ---------- W repack (fp32 -> fp16): 2 outputs per thread ----------
#define WTOTAL (NCAPS * OCT * 4 * 32)
__global__ void __launch_bounds__(256)
repack_w_kernel(const float* __restrict__ W) {
    const int tid = blockIdx.x * blockDim.x + threadIdx.x;
    #pragma unroll
    for (int h = 0; h < 2; ++h) {
        const int idx = tid + h * (WTOTAL / 2);
        const int oq = idx & 3;
        const int rq = (idx >> 2) & 7;
        const int ip = (idx >> 5) & 3;
        const int rb = idx >> 7;               // n*OCT + g
        const float* row = W + (size_t)(rb * 8 + rq) * 128;
        const float4 fe = *(const float4*)(row + (2*ip)     * 16 + 4*oq);
        const float4 fo = *(const float4*)(row + (2*ip + 1) * 16 + 4*oq);
        __half2 h0 = __floats2half2_rn(fe.x, fe.y);
        __half2 h1 = __floats2half2_rn(fe.z, fe.w);
        __half2 h2 = __floats2half2_rn(fo.x, fo.y);
        __half2 h3 = __floats2half2_rn(fo.z, fo.w);
        uint4 o;
        o.x = *(uint32_t*)&h0; o.y = *(uint32_t*)&h1;
        o.z = *(uint32_t*)&h2; o.w = *(uint32_t*)&h3;
        caps_Wh[idx] = o;
    }
}

__global__ void __launch_bounds__(NTHREADS, 1)
caps_kernel(const float* __restrict__ x,
            float* __restrict__ out) {
    extern __shared__ char smem[];
    __half* p   = (__half*)smem;
    float* sred = (float*)(smem + SRED_OFF);
    float* wred = (float*)(smem + WRED_OFF);
    float* vdot = (float*)(smem + VDOT_OFF);

    const int n  = blockIdx.y;
    const int b0 = blockIdx.x * BT;
    const int t  = threadIdx.x;
    const int wid  = t >> 5;
    const int lane = t & 31;

    // ======== Phase 1: priors GEMM (octet mapping, fp16 W) ========
    // lane = (rq 0..7, oq 0..3)
    {
        const int rq = lane >> 2;
        const int oq = lane & 3;
        const int q  = oq >> 1;            // 16B chunk this lane's H4 lives in
        const int sub = (oq & 1) << 2;     // half-offset within chunk (halves)
        #pragma unroll 1
        for (int j = 0; j < JIT; ++j) {
            const int g = wid + j * NWARP;
            const int r = g * 8 + rq;
            const int s = (r >> 2) & 1;
            const int choff = ((q ^ s) << 3) + sub;   // halves within row
            // W: 4 LDG.128, each warp-instr covers 512B contiguous
            const uint4* wh =
                caps_Wh + ((size_t)(n * OCT + g) * 4) * 32 + rq * 4 + oq;
            uint4 wc4[4];
            #pragma unroll
            for (int ip = 0; ip < 4; ++ip) wc4[ip] = wh[ip * 32];
            // convert once: 16 packed f32x2 (i ascending)
            u64 wpk[16];
            #pragma unroll
            for (int ip = 0; ip < 4; ++ip) {
                wpk[4*ip + 0] = h2pk(wc4[ip].x);   // i=2ip,   o0 o1
                wpk[4*ip + 1] = h2pk(wc4[ip].y);   // i=2ip,   o2 o3
                wpk[4*ip + 2] = h2pk(wc4[ip].z);   // i=2ip+1, o0 o1
                wpk[4*ip + 3] = h2pk(wc4[ip].w);   // i=2ip+1, o2 o3
            }

            // b-pair split keeps live registers bounded
            #pragma unroll
            for (int bp = 0; bp < 2; ++bp) {
                float xv[2][CI];
                #pragma unroll
                for (int bb = 0; bb < 2; ++bb) {
                    const int b = bp * 2 + bb;
                    const float4* xp =
                        (const float4*)(x + ((size_t)(b0 + b) * NR + r) * CI);
                    const float4 x0 = xp[0], x1 = xp[1];
                    xv[bb][0]=x0.x; xv[bb][1]=x0.y; xv[bb][2]=x0.z; xv[bb][3]=x0.w;
                    xv[bb][4]=x1.x; xv[bb][5]=x1.y; xv[bb][6]=x1.z; xv[bb][7]=x1.w;
                }
                u64 acc[2][2];
                acc[0][0]=0ull; acc[0][1]=0ull; acc[1][0]=0ull; acc[1][1]=0ull;
                #pragma unroll
                for (int i = 0; i < CI; ++i) {
                    const u64 wlo = wpk[(i >> 1) * 4 + (i & 1) * 2 + 0];
                    const u64 whi = wpk[(i >> 1) * 4 + (i & 1) * 2 + 1];
                    #pragma unroll
                    for (int bb = 0; bb < 2; ++bb) {
                        const u64 xx = pack2(xv[bb][i]);
                        fma2(acc[bb][0], xx, wlo);
                        fma2(acc[bb][1], xx, whi);
                    }
                }
                #pragma unroll
                for (int bb = 0; bb < 2; ++bb) {
                    const int b = bp * 2 + bb;
                    const float2 f0 = unpack2(acc[bb][0]);
                    const float2 f1 = unpack2(acc[bb][1]);
                    H4 h;
                    h.a = __floats2half2_rn(f0.x, f0.y);
                    h.b = __floats2half2_rn(f1.x, f1.y);
                    *(H4*)(p + (size_t)(b * NR + r) * PSTR + choff) = h;
                }
            }
        }
    }
    __syncthreads();

    // ======== Phase 2: routing, streamed rows, max-free softmax ========
    const int b    = t / TPB;      // 0..3
    const int tb   = t % TPB;      // 0..191
    const int wl   = tb >> 5;      // warp in group 0..5
    const int bid  = b + 1;
    const __half* pb = p + (size_t)b * NR * PSTR;
    float* sredb = sred + b * WPG * CO;
    float* wredb = wred + b * WPG;
    float* vdotb = vdot + b * CO;

    // ---- v0 = squash(mean_r p_r): one streamed pass ----
    {
        float S[CO];
        #pragma unroll
        for (int o = 0; o < CO; ++o) S[o] = 0.f;
        #pragma unroll
        for (int k = 0; k < KPT; ++k) {
            float f[CO];
            load_row_sw(pb, tb + k * TPB, f);
            #pragma unroll
            for (int o = 0; o < CO; ++o) S[o] += f[o];
        }
        reduce_s16(S, lane, sredb + wl * CO);
        bar_group(bid);
        if (tb < CO) {
            float s = 0.f;
            #pragma unroll
            for (int w = 0; w < WPG; ++w) s += sredb[w * CO + tb];
            const float v = s * (1.0f / NR);
            float sq = v * v;
            #pragma unroll
            for (int off = 8; off; off >>= 1)
                sq += __shfl_xor_sync(0xffffu, sq, off);
            const float coef = sq / ((1.f + sq) * sqrtf(sq));
            vdotb[tb] = v * coef;
        }
        bar_group(bid);
    }

    // ---- rounds 1 and 2: single fused streamed pass per round ----
    #pragma unroll
    for (int round = 0; round < 2; ++round) {
        // vd via 4x LDS.128
        float vd[CO];
        {
            const float4* vv = (const float4*)vdotb;
            #pragma unroll
            for (int q4 = 0; q4 < 4; ++q4) {
                const float4 v = vv[q4];
                vd[4*q4+0] = v.x; vd[4*q4+1] = v.y;
                vd[4*q4+2] = v.z; vd[4*q4+3] = v.w;
            }
        }

        float S[CO];
        #pragma unroll
        for (int o = 0; o < CO; ++o) S[o] = 0.f;
        float zloc = 0.f;

        #pragma unroll
        for (int k = 0; k < KPT; ++k) {
            float f[CO];
            load_row_sw(pb, tb + k * TPB, f);
            float a = 0.f;
            #pragma unroll
            for (int o = 0; o < CO; ++o) a += f[o] * vd[o];
            const float e = __expf(a);      // max-free: |a| <~ 20, safe
            zloc += e;
            #pragma unroll
            for (int o = 0; o < CO; ++o) S[o] += e * f[o];
        }
        #pragma unroll
        for (int off = 16; off; off >>= 1)
            zloc += __shfl_xor_sync(0xffffffffu, zloc, off);
        if (lane == 0) wredb[wl] = zloc;
        reduce_s16(S, lane, sredb + wl * CO);
        bar_group(bid);

        if (tb < CO) {
            float s = 0.f;
            #pragma unroll
            for (int w = 0; w < WPG; ++w) s += sredb[w * CO + tb];
            float Z = wredb[0];
            #pragma unroll
            for (int w = 1; w < WPG; ++w) Z += wredb[w];
            const float v = s / Z;
            float sq = v * v;
            #pragma unroll
            for (int off = 8; off; off >>= 1)
                sq += __shfl_xor_sync(0xffffu, sq, off);
            const float coef = sq / ((1.f + sq) * sqrtf(sq));
            const float res = v * coef;
            if (round == 0)
                vdotb[tb] += res;                       // w = v0 + v1
            else
                out[((size_t)n * NB + (b0 + b)) * CO + tb] = res;
        }
        bar_group(bid);
    }
}

extern "C" void kernel_launch(void* const* d_in, const int* in_sizes, int n_in,
                              void* d_out, int out_size) {
    (void)in_sizes; (void)n_in; (void)out_size;
    const float* x = (const float*)d_in[0];
    const float* W = (const float*)d_in[1];
    float* out = (float*)d_out;

    repack_w_kernel<<<WTOTAL / 2 / 256, 256>>>(W);

    cudaFuncSetAttribute(caps_kernel,
                         cudaFuncAttributeMaxDynamicSharedMemorySize, SMEM_TOTAL);
    dim3 grid(GROUPS, NCAPS);
    caps_kernel<<<grid, NTHREADS, SMEM_TOTAL>>>(x, out);
}

// round 15
// speedup vs baseline: 1.1326x; 1.0307x over previous
#include <cuda_runtime.h>
#include <cuda_fp16.h>
#include <cstdint>

// CapsuleLayer dynamic routing, 3 rounds.
// x: [512, 1152, 8] fp32   W: [10, 1152, 8, 16] fp32   out: [10, 512, 16] fp32
//
// R14 structure (proven 95.5us) + two issue-slot cuts:
//   - v0 pass accumulates row sums in native half2 (HADD2), converting to
//     fp32 once per thread instead of per row (sum order irrelevant;
//     cross-lane reduce stays fp32),
//   - softmax exponent via raw ex2.approx with the routing weight vector
//     pre-scaled by log2(e) at its write site (scale-consistent softmax).
// W pre-pass (fp16): caps_Wh[n][g][ip][rq][oq] uint4 (16B = 8 halves):
//   halves 0..3 = W[g*8+rq][2ip][4oq..4oq+3], 4..7 = same at i=2ip+1.
//   Phase-1 warp instr (fixed ip) reads 512B contiguous -> 4 wf/LDG.128.
// Phase 1: warp = row-octet; lane = (rq 0..7, oq 0..3); W converted once to
//   16 packed f32x2 regs, b-pair split GEMM (FMA2). Priors -> fp16 smem,
//   PSTR=16, 16B-chunk XOR swizzle (chunk q of row r at q ^ ((r>>2)&1)):
//   conflict-free STS.64 and LDS.128.
// Phase 2: 4 groups x 192 threads, 6 rows/thread, three streamed passes
//   (v0, round1, round2), max-free softmax (shift-invariant, |a|<~20):
//   one fused a/e/Z/S pass per round. w = v0, then v0+v1.

#define NCAPS 10
#define NB    512
#define NR    1152
#define CI    8
#define CO    16
#define BT    4
#define NTHREADS 768
#define GROUPS (NB / BT)          // 128
#define TPB   192                 // threads per batch group (6 warps)
#define WPG   6
#define KPT   (NR / TPB)          // 6 rows per thread in routing
#define NWARP (NTHREADS / 32)     // 24
#define OCT   (NR / 8)            // 144 row-octets
#define JIT   (OCT / NWARP)       // 6 octets per warp
#define PSTR  16                  // halves per prior row (exact, swizzled)
#define LOG2E 1.4426950408889634f

// shared memory layout (bytes)
#define P_BYTES    (BT * NR * PSTR * 2)   // 147456 fp16 priors
#define SRED_OFF   P_BYTES
#define SRED_BYTES (BT * WPG * CO * 4)    // 1536
#define WRED_OFF   (SRED_OFF + SRED_BYTES)
#define WRED_BYTES (BT * WPG * 4)         // 96
#define VDOT_OFF   (WRED_OFF + WRED_BYTES)
#define VDOT_BYTES (BT * CO * 4)          // 256 (16B-aligned per group)
#define SMEM_TOTAL (VDOT_OFF + VDOT_BYTES)

// repacked fp16 W: [NCAPS][OCT][4 ip][8 rq][4 oq] x 16B
__device__ __align__(16) uint4 caps_Wh[NCAPS * OCT * 4 * 32];

struct __align__(8) H4 { __half2 a, b; };
typedef unsigned long long u64;

__device__ __forceinline__ void fma2(u64& d, u64 a, u64 b) {
    asm("fma.rn.f32x2 %0, %1, %2, %0;" : "+l"(d) : "l"(a), "l"(b));
}
__device__ __forceinline__ u64 pack2(float x) {
    u64 r; asm("mov.b64 %0, {%1, %1};" : "=l"(r) : "f"(x)); return r;
}
__device__ __forceinline__ u64 packf2(float x, float y) {
    u64 r; asm("mov.b64 %0, {%1, %2};" : "=l"(r) : "f"(x), "f"(y)); return r;
}
__device__ __forceinline__ float2 unpack2(u64 v) {
    float2 f; asm("mov.b64 {%0, %1}, %2;" : "=f"(f.x), "=f"(f.y) : "l"(v));
    return f;
}
__device__ __forceinline__ u64 h2pk(uint32_t h) {    // half2 -> packed f32x2
    const float2 f = __half22float2(*(const __half2*)&h);
    return packf2(f.x, f.y);
}
__device__ __forceinline__ float ex2f(float x) {     // 2^x, one MUFU
    float r; asm("ex2.approx.ftz.f32 %0, %1;" : "=f"(r) : "f"(x)); return r;
}
__device__ __forceinline__ void bar_group(int id) {
    asm volatile("bar.sync %0, %1;" :: "r"(id), "r"(TPB) : "memory");
}

// Load logical row r (16B-chunk swizzled) into f[16] via 2x LDS.128.
__device__ __forceinline__ void load_row_sw(const __half* pb, int r,
                                            float f[CO]) {
    const uint4* base = (const uint4*)(pb + (size_t)r * PSTR);
    const int s = (r >> 2) & 1;
    const uint4 u0 = base[s];        // logical chunk 0
    const uint4 u1 = base[s ^ 1];    // logical chunk 1
    const uint32_t hs[8] = {u0.x, u0.y, u0.z, u0.w, u1.x, u1.y, u1.z, u1.w};
    #pragma unroll
    for (int j = 0; j < 8; ++j) {
        const float2 ff = __half22float2(*(const __half2*)&hs[j]);
        f[2*j]   = ff.x;
        f[2*j+1] = ff.y;
    }
}

// Split-exchange reduce of S[16] over 32 lanes: 16 shfl total.
__device__ __forceinline__ void reduce_s16(float S[CO], int lane,
                                           float* sred_warp) {
    const bool h16 = lane & 16;
    #pragma unroll
    for (int j = 0; j < 8; ++j) {
        const float snd = h16 ? S[j] : S[j + 8];
        const float kp  = h16 ? S[j + 8] : S[j];
        S[j] = kp + __shfl_xor_sync(0xffffffffu, snd, 16);
    }
    const bool h8 = lane & 8;
    #pragma unroll
    for (int j = 0; j < 4; ++j) {
        const float snd = h8 ? S[j] : S[j + 4];
        const float kp  = h8 ? S[j + 4] : S[j];
        S[j] = kp + __shfl_xor_sync(0xffffffffu, snd, 8);
    }
    const bool h4 = lane & 4;
    #pragma unroll
    for (int j = 0; j < 2; ++j) {
        const float snd = h4 ? S[j] : S[j + 2];
        const float kp  = h4 ? S[j + 2] : S[j];
        S[j] = kp + __shfl_xor_sync(0xffffffffu, snd, 4);
    }
    const bool h2 = lane & 2;
    {
        const float snd = h2 ? S[0] : S[1];
        const float kp  = h2 ? S[1] : S[0];
        S[0] = kp + __shfl_xor_sync(0xffffffffu, snd, 2);
    }
    S[0] += __shfl_xor_sync(0xffffffffu, S[0], 1);
    const int comp = ((lane >> 4) & 1) * 8 + ((lane >> 3) & 1) * 4 +
                     ((lane >> 2) & 1) * 2 + ((lane >> 1) & 1);
    if (!(lane & 1)) sred_warp[comp] = S[0];
}

// ---------- W repack (fp32 -> fp16): 2 outputs per thread ----------
#define WTOTAL (NCAPS * OCT * 4 * 32)
__global__ void __launch_bounds__(256)
repack_w_kernel(const float* __restrict__ W) {
    const int tid = blockIdx.x * blockDim.x + threadIdx.x;
    #pragma unroll
    for (int h = 0; h < 2; ++h) {
        const int idx = tid + h * (WTOTAL / 2);
        const int oq = idx & 3;
        const int rq = (idx >> 2) & 7;
        const int ip = (idx >> 5) & 3;
        const int rb = idx >> 7;               // n*OCT + g
        const float* row = W + (size_t)(rb * 8 + rq) * 128;
        const float4 fe = *(const float4*)(row + (2*ip)     * 16 + 4*oq);
        const float4 fo = *(const float4*)(row + (2*ip + 1) * 16 + 4*oq);
        __half2 h0 = __floats2half2_rn(fe.x, fe.y);
        __half2 h1 = __floats2half2_rn(fe.z, fe.w);
        __half2 h2 = __floats2half2_rn(fo.x, fo.y);
        __half2 h3 = __floats2half2_rn(fo.z, fo.w);
        uint4 o;
        o.x = *(uint32_t*)&h0; o.y = *(uint32_t*)&h1;
        o.z = *(uint32_t*)&h2; o.w = *(uint32_t*)&h3;
        caps_Wh[idx] = o;
    }
}

__global__ void __launch_bounds__(NTHREADS, 1)
caps_kernel(const float* __restrict__ x,
            float* __restrict__ out) {
    extern __shared__ char smem[];
    __half* p   = (__half*)smem;
    float* sred = (float*)(smem + SRED_OFF);
    float* wred = (float*)(smem + WRED_OFF);
    float* vdot = (float*)(smem + VDOT_OFF);

    const int n  = blockIdx.y;
    const int b0 = blockIdx.x * BT;
    const int t  = threadIdx.x;
    const int wid  = t >> 5;
    const int lane = t & 31;

    // ======== Phase 1: priors GEMM (octet mapping, fp16 W) ========
    // lane = (rq 0..7, oq 0..3)
    {
        const int rq = lane >> 2;
        const int oq = lane & 3;
        const int q  = oq >> 1;            // 16B chunk this lane's H4 lives in
        const int sub = (oq & 1) << 2;     // half-offset within chunk (halves)
        #pragma unroll 1
        for (int j = 0; j < JIT; ++j) {
            const int g = wid + j * NWARP;
            const int r = g * 8 + rq;
            const int s = (r >> 2) & 1;
            const int choff = ((q ^ s) << 3) + sub;   // halves within row
            // W: 4 LDG.128, each warp-instr covers 512B contiguous
            const uint4* wh =
                caps_Wh + ((size_t)(n * OCT + g) * 4) * 32 + rq * 4 + oq;
            uint4 wc4[4];
            #pragma unroll
            for (int ip = 0; ip < 4; ++ip) wc4[ip] = wh[ip * 32];
            // convert once: 16 packed f32x2 (i ascending)
            u64 wpk[16];
            #pragma unroll
            for (int ip = 0; ip < 4; ++ip) {
                wpk[4*ip + 0] = h2pk(wc4[ip].x);   // i=2ip,   o0 o1
                wpk[4*ip + 1] = h2pk(wc4[ip].y);   // i=2ip,   o2 o3
                wpk[4*ip + 2] = h2pk(wc4[ip].z);   // i=2ip+1, o0 o1
                wpk[4*ip + 3] = h2pk(wc4[ip].w);   // i=2ip+1, o2 o3
            }

            // b-pair split keeps live registers bounded
            #pragma unroll
            for (int bp = 0; bp < 2; ++bp) {
                float xv[2][CI];
                #pragma unroll
                for (int bb = 0; bb < 2; ++bb) {
                    const int b = bp * 2 + bb;
                    const float4* xp =
                        (const float4*)(x + ((size_t)(b0 + b) * NR + r) * CI);
                    const float4 x0 = xp[0], x1 = xp[1];
                    xv[bb][0]=x0.x; xv[bb][1]=x0.y; xv[bb][2]=x0.z; xv[bb][3]=x0.w;
                    xv[bb][4]=x1.x; xv[bb][5]=x1.y; xv[bb][6]=x1.z; xv[bb][7]=x1.w;
                }
                u64 acc[2][2];
                acc[0][0]=0ull; acc[0][1]=0ull; acc[1][0]=0ull; acc[1][1]=0ull;
                #pragma unroll
                for (int i = 0; i < CI; ++i) {
                    const u64 wlo = wpk[(i >> 1) * 4 + (i & 1) * 2 + 0];
                    const u64 whi = wpk[(i >> 1) * 4 + (i & 1) * 2 + 1];
                    #pragma unroll
                    for (int bb = 0; bb < 2; ++bb) {
                        const u64 xx = pack2(xv[bb][i]);
                        fma2(acc[bb][0], xx, wlo);
                        fma2(acc[bb][1], xx, whi);
                    }
                }
                #pragma unroll
                for (int bb = 0; bb < 2; ++bb) {
                    const int b = bp * 2 + bb;
                    const float2 f0 = unpack2(acc[bb][0]);
                    const float2 f1 = unpack2(acc[bb][1]);
                    H4 h;
                    h.a = __floats2half2_rn(f0.x, f0.y);
                    h.b = __floats2half2_rn(f1.x, f1.y);
                    *(H4*)(p + (size_t)(b * NR + r) * PSTR + choff) = h;
                }
            }
        }
    }
    __syncthreads();

    // ======== Phase 2: routing, streamed rows, max-free softmax ========
    const int b    = t / TPB;      // 0..3
    const int tb   = t % TPB;      // 0..191
    const int wl   = tb >> 5;      // warp in group 0..5
    const int bid  = b + 1;
    const __half* pb = p + (size_t)b * NR * PSTR;
    float* sredb = sred + b * WPG * CO;
    float* wredb = wred + b * WPG;
    float* vdotb = vdot + b * CO;

    // ---- v0 = squash(mean_r p_r): one streamed pass, half2 partials ----
    {
        __half2 hacc[8];
        #pragma unroll
        for (int j = 0; j < 8; ++j) hacc[j] = __half2half2(__ushort_as_half(0));
        #pragma unroll
        for (int k = 0; k < KPT; ++k) {
            const int r = tb + k * TPB;
            const uint4* base = (const uint4*)(pb + (size_t)r * PSTR);
            const int s = (r >> 2) & 1;
            const uint4 u0 = base[s];
            const uint4 u1 = base[s ^ 1];
            hacc[0] = __hadd2(hacc[0], *(const __half2*)&u0.x);
            hacc[1] = __hadd2(hacc[1], *(const __half2*)&u0.y);
            hacc[2] = __hadd2(hacc[2], *(const __half2*)&u0.z);
            hacc[3] = __hadd2(hacc[3], *(const __half2*)&u0.w);
            hacc[4] = __hadd2(hacc[4], *(const __half2*)&u1.x);
            hacc[5] = __hadd2(hacc[5], *(const __half2*)&u1.y);
            hacc[6] = __hadd2(hacc[6], *(const __half2*)&u1.z);
            hacc[7] = __hadd2(hacc[7], *(const __half2*)&u1.w);
        }
        float S[CO];
        #pragma unroll
        for (int j = 0; j < 8; ++j) {
            const float2 ff = __half22float2(hacc[j]);
            S[2*j] = ff.x; S[2*j+1] = ff.y;
        }
        reduce_s16(S, lane, sredb + wl * CO);
        bar_group(bid);
        if (tb < CO) {
            float s = 0.f;
            #pragma unroll
            for (int w = 0; w < WPG; ++w) s += sredb[w * CO + tb];
            const float v = s * (1.0f / NR);
            float sq = v * v;
            #pragma unroll
            for (int off = 8; off; off >>= 1)
                sq += __shfl_xor_sync(0xffffu, sq, off);
            const float coef = sq / ((1.f + sq) * sqrtf(sq));
            vdotb[tb] = v * coef * LOG2E;   // pre-scaled for ex2
        }
        bar_group(bid);
    }

    // ---- rounds 1 and 2: single fused streamed pass per round ----
    #pragma unroll
    for (int round = 0; round < 2; ++round) {
        // vd via 4x LDS.128 (holds log2e-scaled weight vector)
        float vd[CO];
        {
            const float4* vv = (const float4*)vdotb;
            #pragma unroll
            for (int q4 = 0; q4 < 4; ++q4) {
                const float4 v = vv[q4];
                vd[4*q4+0] = v.x; vd[4*q4+1] = v.y;
                vd[4*q4+2] = v.z; vd[4*q4+3] = v.w;
            }
        }

        float S[CO];
        #pragma unroll
        for (int o = 0; o < CO; ++o) S[o] = 0.f;
        float zloc = 0.f;

        #pragma unroll
        for (int k = 0; k < KPT; ++k) {
            float f[CO];
            load_row_sw(pb, tb + k * TPB, f);
            float a = 0.f;
            #pragma unroll
            for (int o = 0; o < CO; ++o) a += f[o] * vd[o];
            const float e = ex2f(a);        // a already in log2 units
            zloc += e;
            #pragma unroll
            for (int o = 0; o < CO; ++o) S[o] += e * f[o];
        }
        #pragma unroll
        for (int off = 16; off; off >>= 1)
            zloc += __shfl_xor_sync(0xffffffffu, zloc, off);
        if (lane == 0) wredb[wl] = zloc;
        reduce_s16(S, lane, sredb + wl * CO);
        bar_group(bid);

        if (tb < CO) {
            float s = 0.f;
            #pragma unroll
            for (int w = 0; w < WPG; ++w) s += sredb[w * CO + tb];
            float Z = wredb[0];
            #pragma unroll
            for (int w = 1; w < WPG; ++w) Z += wredb[w];
            const float v = s / Z;
            float sq = v * v;
            #pragma unroll
            for (int off = 8; off; off >>= 1)
                sq += __shfl_xor_sync(0xffffu, sq, off);
            const float coef = sq / ((1.f + sq) * sqrtf(sq));
            const float res = v * coef;
            if (round == 0)
                vdotb[tb] += res * LOG2E;               // w = v0 + v1 (scaled)
            else
                out[((size_t)n * NB + (b0 + b)) * CO + tb] = res;
        }
        bar_group(bid);
    }
}

extern "C" void kernel_launch(void* const* d_in, const int* in_sizes, int n_in,
                              void* d_out, int out_size) {
    (void)in_sizes; (void)n_in; (void)out_size;
    const float* x = (const float*)d_in[0];
    const float* W = (const float*)d_in[1];
    float* out = (float*)d_out;

    repack_w_kernel<<<WTOTAL / 2 / 256, 256>>>(W);

    cudaFuncSetAttribute(caps_kernel,
                         cudaFuncAttributeMaxDynamicSharedMemorySize, SMEM_TOTAL);
    dim3 grid(GROUPS, NCAPS);
    caps_kernel<<<grid, NTHREADS, SMEM_TOTAL>>>(x, out);
}